// round 16
// baseline (speedup 1.0000x reference)
#include <cuda_runtime.h>
#include <cstdint>

// ROI-align pooling R15: R10's dual-bin body (best kernel, 18.9us) with
// setup computed INLINE per-thread -> single kernel launch (saves the ~2.2us
// setup-kernel + launch-gap overhead measured as total-minus-kernel time).
// R3-vs-R4 established that redundant per-thread setup math is ~free at high
// occupancy (issue% has huge headroom under memory stalls).
//
// img (1,128,128,1024) NHWC fp32, rois (1,256,4) [x,y,w,h] px,
// out (1,256,7,7,1024) fp32.

#define POOL  7
#define NROIS 256
#define HH    128
#define WW    128
#define CC    1024
#define NBINS (NROIS * POOL * POOL)   // 12544
#define HALF  (NBINS / 2)             // 6272

struct BinParams {
    int   o00, o01, o10, o11;   // corner offsets in float4 units
    float tx, ty;
};

__device__ __forceinline__ BinParams bin_setup(const float* __restrict__ rois,
                                               int bin)
{
    const int roi = bin / (POOL * POOL);
    const int b49 = bin - roi * (POOL * POOL);
    const int iy  = b49 / POOL;
    const int ix  = b49 - iy * POOL;

    // roi = [x, y, w, h]; c = (int)(roi * 1/16)  (truncation, same as astype)
    const float4 r = reinterpret_cast<const float4*>(rois)[roi];
    const int x0 = (int)(r.x * 0.0625f);
    const int y0 = (int)(r.y * 0.0625f);
    const int w  = (int)(r.z * 0.0625f);
    const int h  = (int)(r.w * 0.0625f);

    // identical fp32 math to reference
    const float sy = (float)iy * ((float)h / (float)POOL);
    const float sx = (float)ix * ((float)w / (float)POOL);
    const float fy = floorf(sy);
    const float fx = floorf(sx);
    const float ty = sy - fy;
    const float tx = sx - fx;

    const int y_lo = (int)fy;
    const int x_lo = (int)fx;
    const int y_hi = min(y_lo + 1, max(h - 1, 0));
    const int x_hi = min(x_lo + 1, max(w - 1, 0));

    const int gy0 = min(max(y0 + y_lo, 0), HH - 1);
    const int gy1 = min(max(y0 + y_hi, 0), HH - 1);
    const int gx0 = min(max(x0 + x_lo, 0), WW - 1);
    const int gx1 = min(max(x0 + x_hi, 0), WW - 1);

    // Fold dead-weight (weight exactly 0) / clamp-identical hi corners onto
    // the lo corner (bit-exact; duplicate addresses merge in L1tex).
    const int ex = (tx != 0.0f && gx1 != gx0) ? gx1 : gx0;
    const int ey = (ty != 0.0f && gy1 != gy0) ? gy1 : gy0;

    const int c4 = CC / 4;
    BinParams p;
    p.o00 = (gy0 * WW + gx0) * c4;
    p.o01 = (gy0 * WW + ex ) * c4;
    p.o10 = (ey  * WW + gx0) * c4;
    p.o11 = (ey  * WW + ex ) * c4;
    p.tx  = tx;
    p.ty  = ty;
    return p;
}

__device__ __forceinline__ float4 lerp2(float4 a, float4 b, float4 c, float4 d,
                                        float tx, float ty)
{
    float4 r;
    float top, bot;
    top = a.x + tx * (b.x - a.x);
    bot = c.x + tx * (d.x - c.x);
    r.x = top + ty * (bot - top);
    top = a.y + tx * (b.y - a.y);
    bot = c.y + tx * (d.y - c.y);
    r.y = top + ty * (bot - top);
    top = a.z + tx * (b.z - a.z);
    bot = c.z + tx * (d.z - c.z);
    r.z = top + ty * (bot - top);
    top = a.w + tx * (b.w - a.w);
    bot = c.w + tx * (d.w - c.w);
    r.w = top + ty * (bot - top);
    return r;
}

__global__ __launch_bounds__(256)
void roi_pool_kernel(const float* __restrict__ img,
                     const float* __restrict__ rois,
                     float* __restrict__ out)
{
    const int t    = threadIdx.x;       // 0..255: one float4 lane
    const int bin0 = blockIdx.x;        // 0..6271
    const int bin1 = bin0 + HALF;       // 6272..12543

    const float4* __restrict__ imgv = reinterpret_cast<const float4*>(img);
    float4* __restrict__ outv = reinterpret_cast<float4*>(out);

    // Inline setup for both bins (redundant across threads; hidden under
    // memory stalls).
    const BinParams p0 = bin_setup(rois, bin0);
    const BinParams p1 = bin_setup(rois, bin1);

    // 8 independent corner loads, compiler-scheduled (R10 operating point:
    // occupancy beats forced per-warp MLP).
    const float4 a0 = imgv[p0.o00 + t];
    const float4 b0 = imgv[p0.o01 + t];
    const float4 c0 = imgv[p0.o10 + t];
    const float4 d0 = imgv[p0.o11 + t];
    const float4 a1 = imgv[p1.o00 + t];
    const float4 b1 = imgv[p1.o01 + t];
    const float4 c1 = imgv[p1.o10 + t];
    const float4 d1 = imgv[p1.o11 + t];

    const float4 r0 = lerp2(a0, b0, c0, d0, p0.tx, p0.ty);
    outv[(size_t)bin0 * (CC / 4) + t] = r0;

    const float4 r1 = lerp2(a1, b1, c1, d1, p1.tx, p1.ty);
    outv[(size_t)bin1 * (CC / 4) + t] = r1;
}

extern "C" void kernel_launch(void* const* d_in, const int* in_sizes, int n_in,
                              void* d_out, int out_size)
{
    const float* img  = (const float*)d_in[0];
    const float* rois = (const float*)d_in[1];
    if (n_in >= 2 && in_sizes[0] < in_sizes[1]) {
        img  = (const float*)d_in[1];
        rois = (const float*)d_in[0];
    }
    float* out = (float*)d_out;

    roi_pool_kernel<<<HALF, 256>>>(img, rois, out);
}

// round 17
// speedup vs baseline: 1.1082x; 1.1082x over previous
#include <cuda_runtime.h>
#include <cstdint>

// ROI-align pooling R16: R10 dual-bin body + per-BLOCK smem setup, 1 launch.
// img (1,128,128,1024) NHWC fp32, rois (1,256,4) [x,y,w,h] px,
// out (1,256,7,7,1024) fp32.
//
// Operating point learned over R1-R15: dual independent bins per 256-thread
// block, compiler-scheduled loads, regs ~32, occ ~8 blocks/SM is the best
// point (~18.9us kernel, L2 service running at ~90% of the ~12.3TB/s chip
// cap). R15 showed per-thread inline setup costs ~4us (issue 54%); R10's
// separate setup kernel costs a launch. Here: threads 0,1 compute the two
// bins' params into smem (setup issue cost ~2/256 of R15), one sync, then
// the unchanged R10 body.

#define POOL  7
#define NROIS 256
#define HH    128
#define WW    128
#define CC    1024
#define NBINS (NROIS * POOL * POOL)   // 12544
#define HALF  (NBINS / 2)             // 6272

struct BinParams {
    int   o00, o01, o10, o11;   // corner offsets in float4 units
    float tx, ty;
};

__device__ __forceinline__ void bin_setup(const float* __restrict__ rois,
                                          int bin, BinParams* out)
{
    const int roi = bin / (POOL * POOL);
    const int b49 = bin - roi * (POOL * POOL);
    const int iy  = b49 / POOL;
    const int ix  = b49 - iy * POOL;

    // roi = [x, y, w, h]; c = (int)(roi * 1/16)  (truncation, same as astype)
    const float4 r = reinterpret_cast<const float4*>(rois)[roi];
    const int x0 = (int)(r.x * 0.0625f);
    const int y0 = (int)(r.y * 0.0625f);
    const int w  = (int)(r.z * 0.0625f);
    const int h  = (int)(r.w * 0.0625f);

    // identical fp32 math to reference
    const float sy = (float)iy * ((float)h / (float)POOL);
    const float sx = (float)ix * ((float)w / (float)POOL);
    const float fy = floorf(sy);
    const float fx = floorf(sx);
    const float ty = sy - fy;
    const float tx = sx - fx;

    const int y_lo = (int)fy;
    const int x_lo = (int)fx;
    const int y_hi = min(y_lo + 1, max(h - 1, 0));
    const int x_hi = min(x_lo + 1, max(w - 1, 0));

    const int gy0 = min(max(y0 + y_lo, 0), HH - 1);
    const int gy1 = min(max(y0 + y_hi, 0), HH - 1);
    const int gx0 = min(max(x0 + x_lo, 0), WW - 1);
    const int gx1 = min(max(x0 + x_hi, 0), WW - 1);

    // Fold dead-weight (weight exactly 0) / clamp-identical hi corners onto
    // the lo corner (bit-exact; cuts dead L2 read traffic).
    const int ex = (tx != 0.0f && gx1 != gx0) ? gx1 : gx0;
    const int ey = (ty != 0.0f && gy1 != gy0) ? gy1 : gy0;

    const int c4 = CC / 4;
    out->o00 = (gy0 * WW + gx0) * c4;
    out->o01 = (gy0 * WW + ex ) * c4;
    out->o10 = (ey  * WW + gx0) * c4;
    out->o11 = (ey  * WW + ex ) * c4;
    out->tx  = tx;
    out->ty  = ty;
}

__device__ __forceinline__ float4 lerp2(float4 a, float4 b, float4 c, float4 d,
                                        float tx, float ty)
{
    float4 r;
    float top, bot;
    top = a.x + tx * (b.x - a.x);
    bot = c.x + tx * (d.x - c.x);
    r.x = top + ty * (bot - top);
    top = a.y + tx * (b.y - a.y);
    bot = c.y + tx * (d.y - c.y);
    r.y = top + ty * (bot - top);
    top = a.z + tx * (b.z - a.z);
    bot = c.z + tx * (d.z - c.z);
    r.z = top + ty * (bot - top);
    top = a.w + tx * (b.w - a.w);
    bot = c.w + tx * (d.w - c.w);
    r.w = top + ty * (bot - top);
    return r;
}

__global__ __launch_bounds__(256)
void roi_pool_kernel(const float* __restrict__ img,
                     const float* __restrict__ rois,
                     float* __restrict__ out)
{
    __shared__ BinParams sp[2];

    const int t    = threadIdx.x;       // 0..255: one float4 lane
    const int bin0 = blockIdx.x;        // 0..6271
    const int bin1 = bin0 + HALF;       // 6272..12543

    // Per-block setup: threads 0 and 1 each handle one bin.
    if (t < 2)
        bin_setup(rois, bin0 + t * HALF, &sp[t]);
    __syncthreads();

    const BinParams p0 = sp[0];
    const BinParams p1 = sp[1];

    const float4* __restrict__ imgv = reinterpret_cast<const float4*>(img);
    float4* __restrict__ outv = reinterpret_cast<float4*>(out);

    // 8 independent corner loads, compiler-scheduled (R10 operating point).
    const float4 a0 = imgv[p0.o00 + t];
    const float4 b0 = imgv[p0.o01 + t];
    const float4 c0 = imgv[p0.o10 + t];
    const float4 d0 = imgv[p0.o11 + t];
    const float4 a1 = imgv[p1.o00 + t];
    const float4 b1 = imgv[p1.o01 + t];
    const float4 c1 = imgv[p1.o10 + t];
    const float4 d1 = imgv[p1.o11 + t];

    const float4 r0 = lerp2(a0, b0, c0, d0, p0.tx, p0.ty);
    outv[(size_t)bin0 * (CC / 4) + t] = r0;

    const float4 r1 = lerp2(a1, b1, c1, d1, p1.tx, p1.ty);
    outv[(size_t)bin1 * (CC / 4) + t] = r1;
}

extern "C" void kernel_launch(void* const* d_in, const int* in_sizes, int n_in,
                              void* d_out, int out_size)
{
    const float* img  = (const float*)d_in[0];
    const float* rois = (const float*)d_in[1];
    if (n_in >= 2 && in_sizes[0] < in_sizes[1]) {
        img  = (const float*)d_in[1];
        rois = (const float*)d_in[0];
    }
    float* out = (float*)d_out;

    roi_pool_kernel<<<HALF, 256>>>(img, rois, out);
}